// round 6
// baseline (speedup 1.0000x reference)
#include <cuda_runtime.h>
#include <cuda_fp16.h>
#include <cstdint>

#define N_USERS 200000
#define N_ITEMS 100000
#define N_TOTAL 300000
#define DIM     64
#define N_EDGES 4800000
#define BATCH   16384

#define SCAN_B  1024
#define NBLK    ((N_TOTAL + SCAN_B - 1) / SCAN_B)   // 293

// ---------------------------------------------------------------------------
// Device-global scratch (no allocation allowed).
// fp16 tables: 38.4 MB each -> L2-resident working set.
// ---------------------------------------------------------------------------
__device__ __half g_B16[N_TOTAL * DIM];             // fp16 copy of base embeddings
__device__ __half g_E1 [N_TOTAL * DIM];             // layer-1 output (fp16)
__device__ __half g_E2 [N_TOTAL * DIM];             // layer-2 output (fp16)
__device__ int    g_rowptr[N_TOTAL + 1];            // CSR row pointers (also cnt)
__device__ int    g_cursor[N_TOTAL];                // scan tmp, then fill cursor
__device__ int    g_bsums [NBLK];                   // per-block scan sums
__device__ int2   g_edges [N_EDGES];                // {src, val bits}, dst-sorted

__device__ __forceinline__ unsigned h2u(__half2 h)
{
    return *reinterpret_cast<unsigned*>(&h);
}

// ---------------------------------------------------------------------------
// base -> fp16 table
// ---------------------------------------------------------------------------
__global__ void convert_base_kernel(const float* __restrict__ ue,
                                    const float* __restrict__ ie,
                                    __half* __restrict__ b16)
{
    const int total4 = N_TOTAL * DIM / 4;
    const int user4  = N_USERS * DIM / 4;
    int i = blockIdx.x * blockDim.x + threadIdx.x;
    if (i >= total4) return;
    float4 v = (i < user4) ? __ldg(reinterpret_cast<const float4*>(ue) + i)
                           : __ldg(reinterpret_cast<const float4*>(ie) + (i - user4));
    uint2 o;
    o.x = h2u(__float22half2_rn(make_float2(v.x, v.y)));
    o.y = h2u(__float22half2_rn(make_float2(v.z, v.w)));
    reinterpret_cast<uint2*>(b16)[i] = o;
}

// ---------------------------------------------------------------------------
// CSR build: zero -> histogram -> 3-step exclusive scan -> bucket scatter
// ---------------------------------------------------------------------------
__global__ void zero_cnt_kernel(int* cnt)
{
    int i = blockIdx.x * blockDim.x + threadIdx.x;
    if (i <= N_TOTAL) cnt[i] = 0;
}

// 4 edges per thread via int4
__global__ void hist_kernel(const int4* __restrict__ ed4, int* cnt)
{
    int i = blockIdx.x * blockDim.x + threadIdx.x;
    if (i >= N_EDGES / 4) return;
    int4 d = __ldg(&ed4[i]);
    atomicAdd(&cnt[d.x], 1);
    atomicAdd(&cnt[d.y], 1);
    atomicAdd(&cnt[d.z], 1);
    atomicAdd(&cnt[d.w], 1);
}

__global__ void scan_block_kernel(const int* __restrict__ cnt, int* tmp, int* bsums)
{
    __shared__ int s[SCAN_B];
    int i = blockIdx.x * SCAN_B + threadIdx.x;
    int v = (i < N_TOTAL) ? cnt[i] : 0;
    s[threadIdx.x] = v;
    __syncthreads();
    #pragma unroll
    for (int off = 1; off < SCAN_B; off <<= 1) {
        int t = (threadIdx.x >= off) ? s[threadIdx.x - off] : 0;
        __syncthreads();
        s[threadIdx.x] += t;
        __syncthreads();
    }
    if (i < N_TOTAL) tmp[i] = s[threadIdx.x] - v;     // exclusive
    if (threadIdx.x == SCAN_B - 1) bsums[blockIdx.x] = s[SCAN_B - 1];
}

__global__ void scan_sums_kernel(int* bsums)
{
    __shared__ int s[512];
    int tid = threadIdx.x;
    int v = (tid < NBLK) ? bsums[tid] : 0;
    s[tid] = v;
    __syncthreads();
    #pragma unroll
    for (int off = 1; off < 512; off <<= 1) {
        int t = (tid >= off) ? s[tid - off] : 0;
        __syncthreads();
        s[tid] += t;
        __syncthreads();
    }
    if (tid < NBLK) bsums[tid] = s[tid] - v;          // exclusive
}

__global__ void finalize_scan_kernel(const int* __restrict__ tmp,
                                     const int* __restrict__ bsums,
                                     int* rowptr, int* cursor)
{
    int i = blockIdx.x * blockDim.x + threadIdx.x;
    if (i >= N_TOTAL) return;
    int v = tmp[i] + bsums[i / SCAN_B];
    rowptr[i] = v;
    cursor[i] = v;
    if (i == 0) rowptr[N_TOTAL] = N_EDGES;
}

// 4 edges per thread, vectorized loads of es/ed/ev
__global__ void csr_scatter_kernel(const int4*   __restrict__ es4,
                                   const int4*   __restrict__ ed4,
                                   const float4* __restrict__ ev4,
                                   int* cursor, int2* edges)
{
    int i = blockIdx.x * blockDim.x + threadIdx.x;
    if (i >= N_EDGES / 4) return;
    int4   s = __ldg(&es4[i]);
    int4   d = __ldg(&ed4[i]);
    float4 v = __ldg(&ev4[i]);
    int p0 = atomicAdd(&cursor[d.x], 1);
    int p1 = atomicAdd(&cursor[d.y], 1);
    int p2 = atomicAdd(&cursor[d.z], 1);
    int p3 = atomicAdd(&cursor[d.w], 1);
    edges[p0] = make_int2(s.x, __float_as_int(v.x));
    edges[p1] = make_int2(s.y, __float_as_int(v.y));
    edges[p2] = make_int2(s.z, __float_as_int(v.z));
    edges[p3] = make_int2(s.w, __float_as_int(v.w));
}

// ---------------------------------------------------------------------------
// fp16 row-wise SpMM, atomic-free. 8 lanes per dst row; each lane owns one
// 16-byte chunk (8 halfs) of the 128-byte row. Unroll 4: batch 4 edge loads,
// then 4 independent gathers -> MLP 4 on the L2-latency chain.
// Accumulation in fp32, output stored fp16.
// ---------------------------------------------------------------------------
__device__ __forceinline__ void fma8(float acc[8], float v, uint4 raw)
{
    float2 f0 = __half22float2(*reinterpret_cast<__half2*>(&raw.x));
    float2 f1 = __half22float2(*reinterpret_cast<__half2*>(&raw.y));
    float2 f2 = __half22float2(*reinterpret_cast<__half2*>(&raw.z));
    float2 f3 = __half22float2(*reinterpret_cast<__half2*>(&raw.w));
    acc[0] += v * f0.x; acc[1] += v * f0.y;
    acc[2] += v * f1.x; acc[3] += v * f1.y;
    acc[4] += v * f2.x; acc[5] += v * f2.y;
    acc[6] += v * f3.x; acc[7] += v * f3.y;
}

__global__ void spmm_h_kernel(const __half* __restrict__ src,
                              __half*       __restrict__ dst,
                              const int*    __restrict__ rowptr,
                              const int2*   __restrict__ edges)
{
    int gid  = blockIdx.x * blockDim.x + threadIdx.x;
    int row  = gid >> 3;
    int lane = gid & 7;
    if (row >= N_TOTAL) return;

    int jb = rowptr[row];
    int je = rowptr[row + 1];

    float acc[8] = {0.f, 0.f, 0.f, 0.f, 0.f, 0.f, 0.f, 0.f};

    int j = jb;
    for (; j + 3 < je; j += 4) {
        int2 p0 = __ldg(&edges[j]);
        int2 p1 = __ldg(&edges[j + 1]);
        int2 p2 = __ldg(&edges[j + 2]);
        int2 p3 = __ldg(&edges[j + 3]);
        uint4 r0 = __ldg(reinterpret_cast<const uint4*>(src + (size_t)p0.x * DIM) + lane);
        uint4 r1 = __ldg(reinterpret_cast<const uint4*>(src + (size_t)p1.x * DIM) + lane);
        uint4 r2 = __ldg(reinterpret_cast<const uint4*>(src + (size_t)p2.x * DIM) + lane);
        uint4 r3 = __ldg(reinterpret_cast<const uint4*>(src + (size_t)p3.x * DIM) + lane);
        fma8(acc, __int_as_float(p0.y), r0);
        fma8(acc, __int_as_float(p1.y), r1);
        fma8(acc, __int_as_float(p2.y), r2);
        fma8(acc, __int_as_float(p3.y), r3);
    }
    for (; j < je; ++j) {
        int2 p0 = __ldg(&edges[j]);
        uint4 r0 = __ldg(reinterpret_cast<const uint4*>(src + (size_t)p0.x * DIM) + lane);
        fma8(acc, __int_as_float(p0.y), r0);
    }

    uint4 o;
    o.x = h2u(__float22half2_rn(make_float2(acc[0], acc[1])));
    o.y = h2u(__float22half2_rn(make_float2(acc[2], acc[3])));
    o.z = h2u(__float22half2_rn(make_float2(acc[4], acc[5])));
    o.w = h2u(__float22half2_rn(make_float2(acc[6], acc[7])));
    reinterpret_cast<uint4*>(dst + (size_t)row * DIM)[lane] = o;
}

// ---------------------------------------------------------------------------
// Fused layer-3 + final gather. One warp per batch entry; each lane owns a
// half2 column pair (2 floats). Unroll-2 on the edge loop for MLP.
//   e3 = sum over edges(row) of val * E2[src]
//   light = (base_fp32 + E1 + E2 + e3) / 4
// Output layout: [users_emb B*64][items_emb B*64][scores B]
// ---------------------------------------------------------------------------
__device__ __forceinline__ float2 final_row(int row,
                                            const float*  __restrict__ base_row_ptr,
                                            const __half* __restrict__ e1,
                                            const __half* __restrict__ e2,
                                            const int*    __restrict__ rowptr,
                                            const int2*   __restrict__ edges,
                                            int lane)
{
    float ax = 0.f, ay = 0.f;
    int jb = rowptr[row];
    int je = rowptr[row + 1];
    int j = jb;
    for (; j + 1 < je; j += 2) {
        int2 p0 = __ldg(&edges[j]);
        int2 p1 = __ldg(&edges[j + 1]);
        __half2 h0 = __ldg(reinterpret_cast<const __half2*>(e2 + (size_t)p0.x * DIM) + lane);
        __half2 h1 = __ldg(reinterpret_cast<const __half2*>(e2 + (size_t)p1.x * DIM) + lane);
        float2 f0 = __half22float2(h0);
        float2 f1 = __half22float2(h1);
        float v0 = __int_as_float(p0.y);
        float v1 = __int_as_float(p1.y);
        ax += v0 * f0.x + v1 * f1.x;
        ay += v0 * f0.y + v1 * f1.y;
    }
    if (j < je) {
        int2 p = __ldg(&edges[j]);
        float v = __int_as_float(p.y);
        float2 f = __half22float2(
            __ldg(reinterpret_cast<const __half2*>(e2 + (size_t)p.x * DIM) + lane));
        ax += v * f.x;
        ay += v * f.y;
    }
    float2 b  = reinterpret_cast<const float2*>(base_row_ptr)[lane];
    float2 f1 = __half22float2(
        __ldg(reinterpret_cast<const __half2*>(e1 + (size_t)row * DIM) + lane));
    float2 f2 = __half22float2(
        __ldg(reinterpret_cast<const __half2*>(e2 + (size_t)row * DIM) + lane));
    return make_float2((b.x + f1.x + f2.x + ax) * 0.25f,
                       (b.y + f1.y + f2.y + ay) * 0.25f);
}

__global__ void gather3_kernel(const float*  __restrict__ ue,
                               const float*  __restrict__ ie,
                               const __half* __restrict__ e1,
                               const __half* __restrict__ e2,
                               const int*    __restrict__ rowptr,
                               const int2*   __restrict__ edges,
                               const int*    __restrict__ users,
                               const int*    __restrict__ items,
                               float*        __restrict__ out)
{
    int w    = (blockIdx.x * blockDim.x + threadIdx.x) >> 5;
    int lane = threadIdx.x & 31;
    if (w >= BATCH) return;

    int u = users[w];
    int t = items[w] + N_USERS;

    float2 uemb = final_row(u, ue + (size_t)u * DIM, e1, e2, rowptr, edges, lane);
    float2 iemb = final_row(t, ie + (size_t)(t - N_USERS) * DIM, e1, e2, rowptr, edges, lane);

    reinterpret_cast<float2*>(out + (size_t)w * DIM)[lane] = uemb;
    reinterpret_cast<float2*>(out + (size_t)BATCH * DIM + (size_t)w * DIM)[lane] = iemb;

    float dot = uemb.x * iemb.x + uemb.y * iemb.y;
    #pragma unroll
    for (int off = 16; off > 0; off >>= 1)
        dot += __shfl_down_sync(0xFFFFFFFFu, dot, off);
    if (lane == 0)
        out[(size_t)2 * BATCH * DIM + w] = dot;
}

// ---------------------------------------------------------------------------
// Launch. Inputs per metadata order:
//  0 user_embed f32  1 item_embed f32  2 edge_src i32  3 edge_dst i32
//  4 edge_val f32    5 users i32       6 items i32
// ---------------------------------------------------------------------------
extern "C" void kernel_launch(void* const* d_in, const int* in_sizes, int n_in,
                              void* d_out, int out_size)
{
    const float* ue = (const float*)d_in[0];
    const float* ie = (const float*)d_in[1];
    const int*   es = (const int*)  d_in[2];
    const int*   ed = (const int*)  d_in[3];
    const float* ev = (const float*)d_in[4];
    const int*   us = (const int*)  d_in[5];
    const int*   it = (const int*)  d_in[6];
    float* out = (float*)d_out;

    __half *b16, *e1, *e2;
    int *rowptr, *cursor, *bsums;
    int2 *edges;
    cudaGetSymbolAddress((void**)&b16,    g_B16);
    cudaGetSymbolAddress((void**)&e1,     g_E1);
    cudaGetSymbolAddress((void**)&e2,     g_E2);
    cudaGetSymbolAddress((void**)&rowptr, g_rowptr);
    cudaGetSymbolAddress((void**)&cursor, g_cursor);
    cudaGetSymbolAddress((void**)&bsums,  g_bsums);
    cudaGetSymbolAddress((void**)&edges,  g_edges);

    const int e4_blocks   = (N_EDGES / 4 + 255) / 256;
    const int node_blocks = (N_TOTAL + 255) / 256;
    const int conv_blocks = (N_TOTAL * DIM / 4 + 255) / 256;
    const int spmm_blocks = (N_TOTAL * 8 + 255) / 256;

    // --- base -> fp16 table ---
    convert_base_kernel<<<conv_blocks, 256>>>(ue, ie, b16);

    // --- CSR build (counting sort of edges by dst) ---
    zero_cnt_kernel     <<<(N_TOTAL + 256) / 256, 256>>>(rowptr);
    hist_kernel         <<<e4_blocks, 256>>>((const int4*)ed, rowptr);
    scan_block_kernel   <<<NBLK, SCAN_B>>>(rowptr, cursor, bsums);
    scan_sums_kernel    <<<1, 512>>>(bsums);
    finalize_scan_kernel<<<node_blocks, 256>>>(cursor, bsums, rowptr, cursor);
    csr_scatter_kernel  <<<e4_blocks, 256>>>((const int4*)es, (const int4*)ed,
                                             (const float4*)ev, cursor, edges);

    // --- 2 fp16 SpMM layers ---
    spmm_h_kernel<<<spmm_blocks, 256>>>(b16, e1, rowptr, edges);
    spmm_h_kernel<<<spmm_blocks, 256>>>(e1,  e2, rowptr, edges);

    // --- fused layer-3 + gather + dot ---
    gather3_kernel<<<(BATCH * 32 + 255) / 256, 256>>>(ue, ie, e1, e2, rowptr, edges,
                                                      us, it, out);
}